// round 7
// baseline (speedup 1.0000x reference)
#include <cuda_runtime.h>
#include <cuda_fp16.h>
#include <stdint.h>

#define DIN 128
#define H1  64
#define H2  32
#define MAXN 100352
#define MAXE 1600000
#define NTHREADS 256
#define SCAN_B 1024

// ---------------------------------------------------------------------------
// Scratch (static device globals)
// ---------------------------------------------------------------------------
__device__ float  g_dinv[MAXN];
__device__ int    g_cnt [MAXN];
__device__ int    g_row [MAXN];
__device__ int    g_cur [MAXN];
__device__ int    g_bsum[SCAN_B];
__device__ int    g_boff[SCAN_B];
__device__ int    g_csr_src[MAXE];        // src only (4B/edge)
__device__ __half g_t1h[MAXN * H1];       // (x@W1)*dinv  fp16
__device__ __half g_h1h[MAXN * H1];       // relu(layer1) fp16
__device__ __half g_t2h[MAXN * H2];       // (h1@W2)*dinv fp16

// ---------------------------------------------------------------------------
// helpers
// ---------------------------------------------------------------------------
__device__ __forceinline__ unsigned h2_to_u(__half2 h) {
    union { __half2 h; unsigned u; } c; c.h = h; return c.u;
}
__device__ __forceinline__ __half2 u_to_h2(unsigned u) {
    union { unsigned u; __half2 h; } c; c.u = u; return c.h;
}
__device__ __forceinline__ unsigned long long fma2(
    unsigned long long a, unsigned long long b, unsigned long long c)
{
    unsigned long long d;
    asm("fma.rn.f32x2 %0, %1, %2, %3;" : "=l"(d) : "l"(a), "l"(b), "l"(c));
    return d;
}
__device__ __forceinline__ unsigned long long mul2(
    unsigned long long a, unsigned long long b)
{
    unsigned long long d;
    asm("mul.rn.f32x2 %0, %1, %2;" : "=l"(d) : "l"(a), "l"(b));
    return d;
}
__device__ __forceinline__ unsigned long long pack2(float s) {
    unsigned long long d;
    asm("mov.b64 %0, {%1, %1};" : "=l"(d) : "f"(s));
    return d;
}
// accumulate 8 halves (uint4) into float2 a[4], unscaled
__device__ __forceinline__ void add_h8(float2 a[4], uint4 v) {
    float2 f;
    f = __half22float2(u_to_h2(v.x)); a[0].x += f.x; a[0].y += f.y;
    f = __half22float2(u_to_h2(v.y)); a[1].x += f.x; a[1].y += f.y;
    f = __half22float2(u_to_h2(v.z)); a[2].x += f.x; a[2].y += f.y;
    f = __half22float2(u_to_h2(v.w)); a[3].x += f.x; a[3].y += f.y;
}

// ---------------------------------------------------------------------------
// preprocessing
// ---------------------------------------------------------------------------
__global__ void k_zero(int N) {
    int i = blockIdx.x * blockDim.x + threadIdx.x;
    if (i < N) g_cnt[i] = 0;
}

// count in-degrees, 4 edges/thread via int4
__global__ void k_cnt(const int* __restrict__ ei, int E) {
    int e4 = blockIdx.x * blockDim.x + threadIdx.x;
    if (e4 * 4 >= E) return;
    int4 d = ((const int4*)(ei + E))[e4];
    atomicAdd(&g_cnt[d.x], 1);
    atomicAdd(&g_cnt[d.y], 1);
    atomicAdd(&g_cnt[d.z], 1);
    atomicAdd(&g_cnt[d.w], 1);
}

// block-level exclusive scan (warp shuffles)
__global__ __launch_bounds__(SCAN_B) void k_scan1(int N) {
    int lane = threadIdx.x & 31, warp = threadIdx.x >> 5;
    int i = blockIdx.x * SCAN_B + threadIdx.x;
    int v = (i < N) ? g_cnt[i] : 0;
    int x = v;
#pragma unroll
    for (int off = 1; off < 32; off <<= 1) {
        int t = __shfl_up_sync(0xffffffff, x, off);
        if (lane >= off) x += t;
    }
    __shared__ int wt[32];
    if (lane == 31) wt[warp] = x;
    __syncthreads();
    if (warp == 0) {
        int y = wt[lane];
        int z = y;
#pragma unroll
        for (int off = 1; off < 32; off <<= 1) {
            int t = __shfl_up_sync(0xffffffff, z, off);
            if (lane >= off) z += t;
        }
        wt[lane] = z - y;
    }
    __syncthreads();
    int base = wt[warp];
    if (i < N) g_row[i] = base + x - v;
    if (threadIdx.x == SCAN_B - 1) g_bsum[blockIdx.x] = base + x;
}

__global__ __launch_bounds__(128) void k_scan2(int nb) {
    int lane = threadIdx.x & 31, warp = threadIdx.x >> 5;
    int v = (threadIdx.x < nb) ? g_bsum[threadIdx.x] : 0;
    int x = v;
#pragma unroll
    for (int off = 1; off < 32; off <<= 1) {
        int t = __shfl_up_sync(0xffffffff, x, off);
        if (lane >= off) x += t;
    }
    __shared__ int wt[4];
    if (lane == 31) wt[warp] = x;
    __syncthreads();
    int base = 0;
    for (int k = 0; k < warp; k++) base += wt[k];
    if (threadIdx.x < nb) g_boff[threadIdx.x] = base + x - v;
}

__global__ void k_scan3(int N) {
    int i = blockIdx.x * blockDim.x + threadIdx.x;
    if (i >= N) return;
    int r = g_row[i] + g_boff[i >> 10];
    g_row[i] = r;
    g_cur[i] = r;
    g_dinv[i] = rsqrtf((float)(g_cnt[i] + 1));
}

// fill CSR (src only), 4 edges/thread
__global__ void k_fill(const int* __restrict__ ei, int E) {
    int e4 = blockIdx.x * blockDim.x + threadIdx.x;
    if (e4 * 4 >= E) return;
    int4 s = ((const int4*)ei)[e4];
    int4 d = ((const int4*)(ei + E))[e4];
    g_csr_src[atomicAdd(&g_cur[d.x], 1)] = s.x;
    g_csr_src[atomicAdd(&g_cur[d.y], 1)] = s.y;
    g_csr_src[atomicAdd(&g_cur[d.z], 1)] = s.z;
    g_csr_src[atomicAdd(&g_cur[d.w], 1)] = s.w;
}

// ---------------------------------------------------------------------------
// GEMM1: t1' = (x @ W1) * dinv[row], fp16 out. Packed f32x2 FMA.
// ---------------------------------------------------------------------------
__global__ __launch_bounds__(128) void k_gemm1(
    const float* __restrict__ x, const float* __restrict__ W1, int N)
{
    __shared__ float w[DIN * H1];
    for (int i = threadIdx.x; i < DIN * H1; i += blockDim.x) w[i] = W1[i];
    __syncthreads();

    int row = blockIdx.x * blockDim.x + threadIdx.x;
    if (row >= N) return;

    const float4* xr = (const float4*)(x + (size_t)row * DIN);
    unsigned long long acc[H1 / 2];
#pragma unroll
    for (int j = 0; j < H1 / 2; j++) acc[j] = 0ull;

#pragma unroll 1
    for (int kk = 0; kk < DIN / 4; kk++) {
        float4 xv = xr[kk];
        int kb = kk * 4;
#pragma unroll
        for (int u = 0; u < 4; u++) {
            float xs = (u == 0) ? xv.x : (u == 1) ? xv.y : (u == 2) ? xv.z : xv.w;
            unsigned long long xx = pack2(xs);
            const ulonglong2* wr = (const ulonglong2*)&w[(kb + u) * H1];
#pragma unroll
            for (int j = 0; j < H1 / 4; j++) {
                ulonglong2 wv = wr[j];
                acc[2 * j + 0] = fma2(xx, wv.x, acc[2 * j + 0]);
                acc[2 * j + 1] = fma2(xx, wv.y, acc[2 * j + 1]);
            }
        }
    }

    unsigned long long dvp = pack2(g_dinv[row]);
    uint4* out = (uint4*)(g_t1h + (size_t)row * H1);
#pragma unroll
    for (int q = 0; q < 8; q++) {
        uint4 o;
        unsigned long long a0 = mul2(acc[4 * q + 0], dvp);
        unsigned long long a1 = mul2(acc[4 * q + 1], dvp);
        unsigned long long a2 = mul2(acc[4 * q + 2], dvp);
        unsigned long long a3 = mul2(acc[4 * q + 3], dvp);
        o.x = h2_to_u(__float22half2_rn(*(float2*)&a0));
        o.y = h2_to_u(__float22half2_rn(*(float2*)&a1));
        o.z = h2_to_u(__float22half2_rn(*(float2*)&a2));
        o.w = h2_to_u(__float22half2_rn(*(float2*)&a3));
        out[q] = o;
    }
}

// ---------------------------------------------------------------------------
// Gather layer 1 (warp per node): h1 = relu(dv * (Σ_e t1'[src] + t1'[node]))
// (self loop is an edge with src==node: contributes t1'[node], NOT *dv)
// 4 lane-groups x 8 lanes; group g handles edges j ≡ g (mod 4).
// ---------------------------------------------------------------------------
__global__ __launch_bounds__(NTHREADS) void k_gather1(int N) {
    int gw = (blockIdx.x * blockDim.x + threadIdx.x) >> 5;
    if (gw >= N) return;
    int node = gw;
    int lane = threadIdx.x & 31;
    int grp  = lane >> 3;      // 0..3
    int sub  = lane & 7;       // 16B chunk within 128B row

    float dv = g_dinv[node];
    float2 a[4] = {{0,0},{0,0},{0,0},{0,0}};

    if (grp == 0) {  // self term: t1'[node], unscaled
        add_h8(a, ((const uint4*)(g_t1h + (size_t)node * H1))[sub]);
    }

    int start = g_row[node];
    int cnt   = g_cnt[node];
    int j = grp;
#pragma unroll 1
    for (; j + 4 < cnt; j += 8) {
        int s0 = g_csr_src[start + j];
        int s1 = g_csr_src[start + j + 4];
        uint4 v0 = ((const uint4*)(g_t1h + (size_t)s0 * H1))[sub];
        uint4 v1 = ((const uint4*)(g_t1h + (size_t)s1 * H1))[sub];
        add_h8(a, v0);
        add_h8(a, v1);
    }
    if (j < cnt) {
        int s0 = g_csr_src[start + j];
        add_h8(a, ((const uint4*)(g_t1h + (size_t)s0 * H1))[sub]);
    }

    // reduce across the 4 groups (xor 8, 16)
#pragma unroll
    for (int off = 8; off <= 16; off <<= 1) {
#pragma unroll
        for (int i = 0; i < 4; i++) {
            a[i].x += __shfl_xor_sync(0xffffffff, a[i].x, off);
            a[i].y += __shfl_xor_sync(0xffffffff, a[i].y, off);
        }
    }

    if (grp == 0) {
        uint4 o;
        float2 f;
        f.x = fmaxf(a[0].x * dv, 0.f); f.y = fmaxf(a[0].y * dv, 0.f);
        o.x = h2_to_u(__float22half2_rn(f));
        f.x = fmaxf(a[1].x * dv, 0.f); f.y = fmaxf(a[1].y * dv, 0.f);
        o.y = h2_to_u(__float22half2_rn(f));
        f.x = fmaxf(a[2].x * dv, 0.f); f.y = fmaxf(a[2].y * dv, 0.f);
        o.z = h2_to_u(__float22half2_rn(f));
        f.x = fmaxf(a[3].x * dv, 0.f); f.y = fmaxf(a[3].y * dv, 0.f);
        o.w = h2_to_u(__float22half2_rn(f));
        ((uint4*)(g_h1h + (size_t)node * H1))[sub] = o;
    }
}

// ---------------------------------------------------------------------------
// GEMM2: t2' = (h1 @ W2) * dinv[row], fp16 in, fp16 out, packed FMA
// ---------------------------------------------------------------------------
__global__ __launch_bounds__(NTHREADS) void k_gemm2(
    const float* __restrict__ W2, int N)
{
    __shared__ float w[H1 * H2];
    for (int i = threadIdx.x; i < H1 * H2; i += blockDim.x) w[i] = W2[i];
    __syncthreads();

    int row = blockIdx.x * blockDim.x + threadIdx.x;
    if (row >= N) return;

    const uint4* hr = (const uint4*)(g_h1h + (size_t)row * H1);
    unsigned long long acc[H2 / 2];
#pragma unroll
    for (int j = 0; j < H2 / 2; j++) acc[j] = 0ull;

#pragma unroll 1
    for (int kk = 0; kk < 8; kk++) {       // 8 uint4 = 64 halves
        uint4 v = hr[kk];
        float2 hf[4];
        hf[0] = __half22float2(u_to_h2(v.x));
        hf[1] = __half22float2(u_to_h2(v.y));
        hf[2] = __half22float2(u_to_h2(v.z));
        hf[3] = __half22float2(u_to_h2(v.w));
        int kb = kk * 8;
#pragma unroll
        for (int u = 0; u < 8; u++) {
            float hv = (u & 1) ? hf[u >> 1].y : hf[u >> 1].x;
            unsigned long long hh = pack2(hv);
            const ulonglong2* wr = (const ulonglong2*)&w[(kb + u) * H2];
#pragma unroll
            for (int j = 0; j < H2 / 4; j++) {
                ulonglong2 wv = wr[j];
                acc[2 * j + 0] = fma2(hh, wv.x, acc[2 * j + 0]);
                acc[2 * j + 1] = fma2(hh, wv.y, acc[2 * j + 1]);
            }
        }
    }

    unsigned long long dvp = pack2(g_dinv[row]);
    uint4* out = (uint4*)(g_t2h + (size_t)row * H2);
#pragma unroll
    for (int q = 0; q < 4; q++) {
        uint4 o;
        unsigned long long a0 = mul2(acc[4 * q + 0], dvp);
        unsigned long long a1 = mul2(acc[4 * q + 1], dvp);
        unsigned long long a2 = mul2(acc[4 * q + 2], dvp);
        unsigned long long a3 = mul2(acc[4 * q + 3], dvp);
        o.x = h2_to_u(__float22half2_rn(*(float2*)&a0));
        o.y = h2_to_u(__float22half2_rn(*(float2*)&a1));
        o.z = h2_to_u(__float22half2_rn(*(float2*)&a2));
        o.w = h2_to_u(__float22half2_rn(*(float2*)&a3));
        out[q] = o;
    }
}

// ---------------------------------------------------------------------------
// Gather layer 2 (warp per node): out = dv * (Σ_e t2'[src] + t2'[node])
// 8 lane-groups x 4 lanes (row = 64B); group g handles edges j ≡ g (mod 8).
// ---------------------------------------------------------------------------
__global__ __launch_bounds__(NTHREADS) void k_gather2(float* __restrict__ out, int N) {
    int gw = (blockIdx.x * blockDim.x + threadIdx.x) >> 5;
    if (gw >= N) return;
    int node = gw;
    int lane = threadIdx.x & 31;
    int grp  = lane >> 2;      // 0..7
    int sub  = lane & 3;       // 16B chunk within 64B row

    float dv = g_dinv[node];
    float2 a[4] = {{0,0},{0,0},{0,0},{0,0}};

    if (grp == 0) {  // self term: t2'[node], unscaled
        add_h8(a, ((const uint4*)(g_t2h + (size_t)node * H2))[sub]);
    }

    int start = g_row[node];
    int cnt   = g_cnt[node];
    int j = grp;
#pragma unroll 1
    for (; j < cnt; j += 8) {
        int s0 = g_csr_src[start + j];
        add_h8(a, ((const uint4*)(g_t2h + (size_t)s0 * H2))[sub]);
    }

    // reduce across the 8 groups (xor 4, 8, 16)
#pragma unroll
    for (int off = 4; off <= 16; off <<= 1) {
#pragma unroll
        for (int i = 0; i < 4; i++) {
            a[i].x += __shfl_xor_sync(0xffffffff, a[i].x, off);
            a[i].y += __shfl_xor_sync(0xffffffff, a[i].y, off);
        }
    }

    if (grp == 0) {
        float4* o = (float4*)(out + (size_t)node * H2 + sub * 8);
        o[0] = make_float4(a[0].x * dv, a[0].y * dv, a[1].x * dv, a[1].y * dv);
        o[1] = make_float4(a[2].x * dv, a[2].y * dv, a[3].x * dv, a[3].y * dv);
    }
}

// ---------------------------------------------------------------------------
// Launch
// ---------------------------------------------------------------------------
extern "C" void kernel_launch(void* const* d_in, const int* in_sizes, int n_in,
                              void* d_out, int out_size)
{
    const float* x  = (const float*)d_in[0];
    const int*   ei = (const int*)d_in[1];
    const float* W1 = (const float*)d_in[2];
    const float* W2 = (const float*)d_in[3];
    float*       out = (float*)d_out;

    int N = in_sizes[0] / DIN;
    int E = in_sizes[1] / 2;
    int E4 = E / 4;
    int nb = (N + SCAN_B - 1) / SCAN_B;

    k_zero <<<(N + NTHREADS - 1) / NTHREADS, NTHREADS>>>(N);
    k_cnt  <<<(E4 + NTHREADS - 1) / NTHREADS, NTHREADS>>>(ei, E);
    k_scan1<<<nb, SCAN_B>>>(N);
    k_scan2<<<1, 128>>>(nb);
    k_scan3<<<(N + NTHREADS - 1) / NTHREADS, NTHREADS>>>(N);
    k_fill <<<(E4 + NTHREADS - 1) / NTHREADS, NTHREADS>>>(ei, E);

    k_gemm1<<<(N + 127) / 128, 128>>>(x, W1, N);

    {
        long long th = (long long)N * 32;
        k_gather1<<<(int)((th + NTHREADS - 1) / NTHREADS), NTHREADS>>>(N);
    }

    k_gemm2<<<(N + NTHREADS - 1) / NTHREADS, NTHREADS>>>(W2, N);

    {
        long long th = (long long)N * 32;
        k_gather2<<<(int)((th + NTHREADS - 1) / NTHREADS), NTHREADS>>>(out, N);
    }
}